// round 1
// baseline (speedup 1.0000x reference)
#include <cuda_runtime.h>
#include <cuda_bf16.h>
#include <cstdint>

// ---------------------------------------------------------------------------
// DiGCN on GB300.
//   Per block: y0 = x@L + (sum of biases); y1 = x@C1; y2 = x@C2  (one GEMM, N=192)
//   then x_next[n] = y0[n] + sum_{e in CSR1[n]} w_e*y1[src_e] + sum_{CSR2[n]} w_e*y2[src_e]
//   CSR (by dst) built once per launch, reused by all 3 blocks.
//   GEMM uses packed fma.rn.f32x2 (2x FFMA throughput on sm_103a).
// ---------------------------------------------------------------------------

#define N_NODES   200000
#define N_EDGES   3200000
#define NPG       50000     // nodes per graph
#define NGRAPH    4
#define HID       64

// ---------------- scratch (static device memory; no allocation) ------------
__device__ float g_y0[(size_t)N_NODES * HID];
__device__ float g_y1[(size_t)N_NODES * HID];
__device__ float g_y2[(size_t)N_NODES * HID];
__device__ float g_x [(size_t)N_NODES * HID];

__device__ int   g_deg1[N_NODES];      // becomes cursor after scan
__device__ int   g_deg2[N_NODES];
__device__ int   g_rs1[N_NODES + 1];
__device__ int   g_rs2[N_NODES + 1];
__device__ int   g_bsum1[128];
__device__ int   g_bsum2[128];
__device__ int2  g_e1[N_EDGES];        // packed (src, bitcast weight)
__device__ int2  g_e2[N_EDGES];

__device__ float g_s0[N_NODES];
__device__ float g_s1[N_NODES];
__device__ float g_s2[N_NODES];
__device__ float g_x3[N_NODES];

// ---------------- small helpers --------------------------------------------
__device__ __forceinline__ void fma2(unsigned long long &d,
                                     unsigned long long a,
                                     unsigned long long b) {
    asm("fma.rn.f32x2 %0, %1, %2, %0;" : "+l"(d) : "l"(a), "l"(b));
}
__device__ __forceinline__ unsigned long long rep2(float x) {
    unsigned long long r;
    unsigned u = __float_as_uint(x);
    asm("mov.b64 %0, {%1, %1};" : "=l"(r) : "r"(u));
    return r;
}

// ---------------- CSR build kernels -----------------------------------------
__global__ void k_zero(int* __restrict__ p, int n) {
    int i = blockIdx.x * blockDim.x + threadIdx.x;
    if (i < n) p[i] = 0;
}

__global__ void k_hist(const int* __restrict__ dst, int* __restrict__ deg, int E) {
    int e = blockIdx.x * blockDim.x + threadIdx.x;
    if (e < E) atomicAdd(&deg[dst[e]], 1);
}

// per-block (2048 elems) sums
__global__ void k_scan_sums(const int* __restrict__ deg, int* __restrict__ bsum, int n) {
    __shared__ int sh[16];
    int tid = threadIdx.x;
    int base = blockIdx.x * 2048 + tid * 4;
    int s = 0;
#pragma unroll
    for (int c = 0; c < 4; ++c) if (base + c < n) s += deg[base + c];
#pragma unroll
    for (int o = 16; o; o >>= 1) s += __shfl_xor_sync(0xffffffffu, s, o);
    if ((tid & 31) == 0) sh[tid >> 5] = s;
    __syncthreads();
    if (tid < 16) {
        int v = sh[tid];
#pragma unroll
        for (int o = 8; o; o >>= 1) v += __shfl_xor_sync(0x0000ffffu, v, o);
        if (tid == 0) bsum[blockIdx.x] = v;
    }
}

__global__ void k_scan_bsum(int* __restrict__ bsum, int nb) {
    if (blockIdx.x == 0 && threadIdx.x == 0) {
        int a = 0;
        for (int i = 0; i < nb; ++i) { int t = bsum[i]; bsum[i] = a; a += t; }
    }
}

// write exclusive scan -> rs, and cursor (in-place over deg)
__global__ void k_scan_write(int* __restrict__ deg, const int* __restrict__ bsum,
                             int* __restrict__ rs, int n, int total) {
    __shared__ int wsum[16];
    int tid = threadIdx.x;
    int lane = tid & 31, wid = tid >> 5;
    int base = blockIdx.x * 2048 + tid * 4;
    int v[4]; int s = 0;
#pragma unroll
    for (int c = 0; c < 4; ++c) { v[c] = (base + c < n) ? deg[base + c] : 0; s += v[c]; }
    int si = s;
#pragma unroll
    for (int o = 1; o < 32; o <<= 1) {
        int t = __shfl_up_sync(0xffffffffu, si, o);
        if (lane >= o) si += t;
    }
    if (lane == 31) wsum[wid] = si;
    __syncthreads();
    if (tid < 16) {
        int t = wsum[tid];
#pragma unroll
        for (int o = 1; o < 16; o <<= 1) {
            int u = __shfl_up_sync(0x0000ffffu, t, o);
            if (tid >= o) t += u;
        }
        wsum[tid] = t;
    }
    __syncthreads();
    int bbase = (wid == 0) ? 0 : wsum[wid - 1];
    int off = bsum[blockIdx.x] + bbase + (si - s);
#pragma unroll
    for (int c = 0; c < 4; ++c) {
        if (base + c < n) { rs[base + c] = off; deg[base + c] = off; off += v[c]; }
    }
    if (blockIdx.x == 0 && tid == 0) rs[n] = total;
}

__global__ void k_fill(const int* __restrict__ src, const int* __restrict__ dst,
                       const float* __restrict__ w, int* __restrict__ cur,
                       int2* __restrict__ out, int E) {
    int e = blockIdx.x * blockDim.x + threadIdx.x;
    if (e < E) {
        int pos = atomicAdd(&cur[dst[e]], 1);
        out[pos] = make_int2(src[e], __float_as_int(w[e]));
    }
}

// ---------------- GEMM: [M x K] @ [K x 192] -> Y0|Y1|Y2 (each M x 64) -------
// BM=128, BN=192, 256 threads, 8m x 12n micro-tile, f32x2 packed FMA.
template <int K>
__global__ void __launch_bounds__(256, 1)
k_gemm(const float* __restrict__ X,
       const float* __restrict__ W0, const float* __restrict__ W1, const float* __restrict__ W2,
       const float* __restrict__ B0, const float* __restrict__ B1, const float* __restrict__ B2,
       float* __restrict__ Y0, float* __restrict__ Y1, float* __restrict__ Y2, int M)
{
    extern __shared__ float smem[];
    float* Xst = smem;              // [K][128]  (k-major, m contiguous)
    float* Ws  = smem + K * 128;    // [K][192]
    float* cb  = Ws + K * 192;      // [64] combined bias

    const int tid = threadIdx.x;
    const int r0  = blockIdx.x * 128;

    if (tid < 64) cb[tid] = B0[tid] + B1[tid] + B2[tid];

    // load X^T: conflict-free STS (consecutive tids -> consecutive m)
#pragma unroll
    for (int p = 0; p < K / 8; ++p) {
        int idx = p * 256 + tid;
        int row = idx & 127;
        int kc  = idx >> 7;           // float4 index along K
        float4 v = make_float4(0.f, 0.f, 0.f, 0.f);
        int grow = r0 + row;
        if (grow < M) v = *reinterpret_cast<const float4*>(&X[(size_t)grow * K + kc * 4]);
        Xst[(kc * 4 + 0) * 128 + row] = v.x;
        Xst[(kc * 4 + 1) * 128 + row] = v.y;
        Xst[(kc * 4 + 2) * 128 + row] = v.z;
        Xst[(kc * 4 + 3) * 128 + row] = v.w;
    }
    // load W concat: col j<64 -> W0, <128 -> W1, else W2
#pragma unroll
    for (int p = 0; p < (K * 48) / 256; ++p) {
        int idx = p * 256 + tid;       // float4 index
        int j4 = idx % 48, k = idx / 48;
        int j = j4 * 4;
        const float* Wm = (j < 64) ? W0 : ((j < 128) ? W1 : W2);
        int jj = j & 63;
        float4 v = *reinterpret_cast<const float4*>(&Wm[k * 64 + jj]);
        *reinterpret_cast<float4*>(&Ws[k * 192 + j]) = v;
    }
    __syncthreads();

    const int tx = tid & 15, ty = tid >> 4;
    const int mb = ty * 8, nb = tx * 12;

    unsigned long long acc[4][12];
#pragma unroll
    for (int p = 0; p < 4; ++p)
#pragma unroll
        for (int j = 0; j < 12; ++j) acc[p][j] = 0ull;

#pragma unroll 8
    for (int k = 0; k < K; ++k) {
        const unsigned long long* ap =
            reinterpret_cast<const unsigned long long*>(&Xst[k * 128 + mb]);
        unsigned long long a0 = ap[0], a1 = ap[1], a2 = ap[2], a3 = ap[3];
        float4 b0 = *reinterpret_cast<const float4*>(&Ws[k * 192 + nb]);
        float4 b1 = *reinterpret_cast<const float4*>(&Ws[k * 192 + nb + 4]);
        float4 b2 = *reinterpret_cast<const float4*>(&Ws[k * 192 + nb + 8]);
        unsigned long long r[12];
        r[0] = rep2(b0.x); r[1] = rep2(b0.y); r[2]  = rep2(b0.z); r[3]  = rep2(b0.w);
        r[4] = rep2(b1.x); r[5] = rep2(b1.y); r[6]  = rep2(b1.z); r[7]  = rep2(b1.w);
        r[8] = rep2(b2.x); r[9] = rep2(b2.y); r[10] = rep2(b2.z); r[11] = rep2(b2.w);
#pragma unroll
        for (int j = 0; j < 12; ++j) {
            fma2(acc[0][j], a0, r[j]);
            fma2(acc[1][j], a1, r[j]);
            fma2(acc[2][j], a2, r[j]);
            fma2(acc[3][j], a3, r[j]);
        }
    }

#pragma unroll
    for (int p = 0; p < 4; ++p) {
#pragma unroll
        for (int h = 0; h < 2; ++h) {
            int row = r0 + mb + 2 * p + h;
            if (row >= M) continue;
#pragma unroll
            for (int j = 0; j < 12; ++j) {
                unsigned u = (h == 0) ? (unsigned)acc[p][j] : (unsigned)(acc[p][j] >> 32);
                float f = __uint_as_float(u);
                int col = nb + j;
                if (col < 64)       Y0[(size_t)row * 64 + col]       = f + cb[col];
                else if (col < 128) Y1[(size_t)row * 64 + col - 64]  = f;
                else                Y2[(size_t)row * 64 + col - 128] = f;
            }
        }
    }
}

// ---------------- conv + combine (hidden=64): warp per node -----------------
__global__ void k_conv64(const float* __restrict__ y0, const float* __restrict__ y1,
                         const float* __restrict__ y2,
                         const int* __restrict__ rs1, const int2* __restrict__ e1,
                         const int* __restrict__ rs2, const int2* __restrict__ e2,
                         float* __restrict__ xout, int M)
{
    int n = (blockIdx.x * blockDim.x + threadIdx.x) >> 5;
    if (n >= M) return;
    int lane = threadIdx.x & 31;
    float2 acc = *reinterpret_cast<const float2*>(&y0[(size_t)n * 64 + lane * 2]);

    int p = rs1[n], pe = rs1[n + 1];
    for (; p + 2 <= pe; p += 2) {
        int2 ea = e1[p], eb = e1[p + 1];
        float2 va = *reinterpret_cast<const float2*>(&y1[(size_t)ea.x * 64 + lane * 2]);
        float2 vb = *reinterpret_cast<const float2*>(&y1[(size_t)eb.x * 64 + lane * 2]);
        float wa = __int_as_float(ea.y), wb = __int_as_float(eb.y);
        acc.x = fmaf(wa, va.x, acc.x); acc.y = fmaf(wa, va.y, acc.y);
        acc.x = fmaf(wb, vb.x, acc.x); acc.y = fmaf(wb, vb.y, acc.y);
    }
    if (p < pe) {
        int2 ea = e1[p];
        float2 va = *reinterpret_cast<const float2*>(&y1[(size_t)ea.x * 64 + lane * 2]);
        float wa = __int_as_float(ea.y);
        acc.x = fmaf(wa, va.x, acc.x); acc.y = fmaf(wa, va.y, acc.y);
    }

    p = rs2[n]; pe = rs2[n + 1];
    for (; p + 2 <= pe; p += 2) {
        int2 ea = e2[p], eb = e2[p + 1];
        float2 va = *reinterpret_cast<const float2*>(&y2[(size_t)ea.x * 64 + lane * 2]);
        float2 vb = *reinterpret_cast<const float2*>(&y2[(size_t)eb.x * 64 + lane * 2]);
        float wa = __int_as_float(ea.y), wb = __int_as_float(eb.y);
        acc.x = fmaf(wa, va.x, acc.x); acc.y = fmaf(wa, va.y, acc.y);
        acc.x = fmaf(wb, vb.x, acc.x); acc.y = fmaf(wb, vb.y, acc.y);
    }
    if (p < pe) {
        int2 ea = e2[p];
        float2 va = *reinterpret_cast<const float2*>(&y2[(size_t)ea.x * 64 + lane * 2]);
        float wa = __int_as_float(ea.y);
        acc.x = fmaf(wa, va.x, acc.x); acc.y = fmaf(wa, va.y, acc.y);
    }

    *reinterpret_cast<float2*>(&xout[(size_t)n * 64 + lane * 2]) = acc;
}

// ---------------- block3 GEMM (64 -> 3 cols): warp per node -----------------
__global__ void k_gemm3(const float* __restrict__ X,
                        const float* __restrict__ w0, const float* __restrict__ w1,
                        const float* __restrict__ w2,
                        const float* __restrict__ b0, const float* __restrict__ b1,
                        const float* __restrict__ b2,
                        float* __restrict__ s0, float* __restrict__ s1,
                        float* __restrict__ s2, int M)
{
    __shared__ float ws[3][64];
    int tid = threadIdx.x;
    if (tid < 64) { ws[0][tid] = w0[tid]; ws[1][tid] = w1[tid]; ws[2][tid] = w2[tid]; }
    __syncthreads();
    int n = blockIdx.x * (blockDim.x >> 5) + (tid >> 5);
    if (n >= M) return;
    int lane = tid & 31;
    float2 xv = *reinterpret_cast<const float2*>(&X[(size_t)n * 64 + lane * 2]);
    float p0 = xv.x * ws[0][2 * lane] + xv.y * ws[0][2 * lane + 1];
    float p1 = xv.x * ws[1][2 * lane] + xv.y * ws[1][2 * lane + 1];
    float p2 = xv.x * ws[2][2 * lane] + xv.y * ws[2][2 * lane + 1];
#pragma unroll
    for (int o = 16; o; o >>= 1) {
        p0 += __shfl_xor_sync(0xffffffffu, p0, o);
        p1 += __shfl_xor_sync(0xffffffffu, p1, o);
        p2 += __shfl_xor_sync(0xffffffffu, p2, o);
    }
    if (lane == 0) {
        s0[n] = p0 + (b0[0] + b1[0] + b2[0]);
        s1[n] = p1;
        s2[n] = p2;
    }
}

// ---------------- block3 conv (scalar): thread per node ---------------------
__global__ void k_conv1(const float* __restrict__ s0, const float* __restrict__ s1,
                        const float* __restrict__ s2,
                        const int* __restrict__ rs1, const int2* __restrict__ e1,
                        const int* __restrict__ rs2, const int2* __restrict__ e2,
                        float* __restrict__ x3, int M)
{
    int n = blockIdx.x * blockDim.x + threadIdx.x;
    if (n >= M) return;
    float acc = s0[n];
    int p = rs1[n], pe = rs1[n + 1];
    for (; p + 2 <= pe; p += 2) {
        int2 a = e1[p], b = e1[p + 1];
        acc = fmaf(__int_as_float(a.y), __ldg(&s1[a.x]), acc);
        acc = fmaf(__int_as_float(b.y), __ldg(&s1[b.x]), acc);
    }
    if (p < pe) { int2 a = e1[p]; acc = fmaf(__int_as_float(a.y), __ldg(&s1[a.x]), acc); }
    p = rs2[n]; pe = rs2[n + 1];
    for (; p + 2 <= pe; p += 2) {
        int2 a = e2[p], b = e2[p + 1];
        acc = fmaf(__int_as_float(a.y), __ldg(&s2[a.x]), acc);
        acc = fmaf(__int_as_float(b.y), __ldg(&s2[b.x]), acc);
    }
    if (p < pe) { int2 a = e2[p]; acc = fmaf(__int_as_float(a.y), __ldg(&s2[a.x]), acc); }
    x3[n] = acc;
}

// ---------------- readout + output copy -------------------------------------
__global__ void k_readout(const float* __restrict__ x3, float* __restrict__ out,
                          int out_size)
{
    __shared__ float sh[256];
    int g = blockIdx.x;                 // 0..3
    float m = -3.402823466e38f;
    for (int i = threadIdx.x; i < NPG; i += blockDim.x)
        m = fmaxf(m, x3[g * NPG + i]);
    sh[threadIdx.x] = m;
    __syncthreads();
    for (int s = 128; s; s >>= 1) {
        if (threadIdx.x < s) sh[threadIdx.x] = fmaxf(sh[threadIdx.x], sh[threadIdx.x + s]);
        __syncthreads();
    }
    if (threadIdx.x == 0 && g < out_size) out[g] = sh[0];
}

__global__ void k_copy_out(const float* __restrict__ x3, float* __restrict__ out,
                           int out_size)
{
    int i = blockIdx.x * blockDim.x + threadIdx.x;
    if (i >= N_NODES) return;
    float v = x3[i];
    if (4 + i < out_size)            out[4 + i] = v;
    if (4 + N_NODES + i < out_size)  out[4 + N_NODES + i] = v;
}

// ---------------------------------------------------------------------------
extern "C" void kernel_launch(void* const* d_in, const int* in_sizes, int n_in,
                              void* d_out, int out_size)
{
    const int E = N_EDGES, NN = N_NODES;

    const float* x   = (const float*)d_in[0];
    const int*   ei1 = (const int*)  d_in[1];
    const float* ew1 = (const float*)d_in[2];
    const int*   ei2 = (const int*)  d_in[3];
    const float* ew2 = (const float*)d_in[4];
    // num_nodes may or may not occupy slot 5
    int base = (in_sizes[5] == 1) ? 6 : 5;
    const float* W[3][3]; const float* B[3][3];
    for (int blk = 0; blk < 3; ++blk)
        for (int part = 0; part < 3; ++part) {           // 0=ln, 1=c1, 2=c2
            W[blk][part] = (const float*)d_in[base + blk * 6 + part * 2];
            B[blk][part] = (const float*)d_in[base + blk * 6 + part * 2 + 1];
        }

    // scratch pointers
    float *y0, *y1, *y2, *gx, *s0, *s1, *s2, *x3;
    int *deg1, *deg2, *rs1, *rs2, *bs1, *bs2;
    int2 *e1, *e2;
    cudaGetSymbolAddress((void**)&y0, g_y0);
    cudaGetSymbolAddress((void**)&y1, g_y1);
    cudaGetSymbolAddress((void**)&y2, g_y2);
    cudaGetSymbolAddress((void**)&gx, g_x);
    cudaGetSymbolAddress((void**)&s0, g_s0);
    cudaGetSymbolAddress((void**)&s1, g_s1);
    cudaGetSymbolAddress((void**)&s2, g_s2);
    cudaGetSymbolAddress((void**)&x3, g_x3);
    cudaGetSymbolAddress((void**)&deg1, g_deg1);
    cudaGetSymbolAddress((void**)&deg2, g_deg2);
    cudaGetSymbolAddress((void**)&rs1, g_rs1);
    cudaGetSymbolAddress((void**)&rs2, g_rs2);
    cudaGetSymbolAddress((void**)&bs1, g_bsum1);
    cudaGetSymbolAddress((void**)&bs2, g_bsum2);
    cudaGetSymbolAddress((void**)&e1, g_e1);
    cudaGetSymbolAddress((void**)&e2, g_e2);

    const int smem128 = (128 * 128 + 128 * 192 + 64) * 4;  // 164096
    const int smem64  = (64 * 128 + 64 * 192 + 64) * 4;    //  82176
    cudaFuncSetAttribute(k_gemm<128>, cudaFuncAttributeMaxDynamicSharedMemorySize, smem128);
    cudaFuncSetAttribute(k_gemm<64>,  cudaFuncAttributeMaxDynamicSharedMemorySize, smem64);

    const int SB = (NN + 2047) / 2048;        // 98 scan blocks
    const int EG = (E + 255) / 256;           // 12500
    const int NG = (NN + 255) / 256;          // 782
    const int GG = (NN + 127) / 128;          // 1563 gemm blocks
    const int CG = (NN * 32 + 255) / 256;     // 25000 (warp/node)

    // ---- CSR build (both edge sets) ----
    k_zero<<<NG, 256>>>(deg1, NN);
    k_zero<<<NG, 256>>>(deg2, NN);
    k_hist<<<EG, 256>>>(ei1 + E, deg1, E);
    k_hist<<<EG, 256>>>(ei2 + E, deg2, E);
    k_scan_sums<<<SB, 512>>>(deg1, bs1, NN);
    k_scan_sums<<<SB, 512>>>(deg2, bs2, NN);
    k_scan_bsum<<<1, 32>>>(bs1, SB);
    k_scan_bsum<<<1, 32>>>(bs2, SB);
    k_scan_write<<<SB, 512>>>(deg1, bs1, rs1, NN, E);
    k_scan_write<<<SB, 512>>>(deg2, bs2, rs2, NN, E);
    k_fill<<<EG, 256>>>(ei1, ei1 + E, ew1, deg1, e1, E);
    k_fill<<<EG, 256>>>(ei2, ei2 + E, ew2, deg2, e2, E);

    // ---- block 1 (K=128) ----
    k_gemm<128><<<GG, 256, smem128>>>(x, W[0][0], W[0][1], W[0][2],
                                      B[0][0], B[0][1], B[0][2],
                                      y0, y1, y2, NN);
    k_conv64<<<CG, 256>>>(y0, y1, y2, rs1, e1, rs2, e2, gx, NN);

    // ---- block 2 (K=64) ----
    k_gemm<64><<<GG, 256, smem64>>>(gx, W[1][0], W[1][1], W[1][2],
                                    B[1][0], B[1][1], B[1][2],
                                    y0, y1, y2, NN);
    k_conv64<<<CG, 256>>>(y0, y1, y2, rs1, e1, rs2, e2, gx, NN);

    // ---- block 3 (64 -> 1) ----
    k_gemm3<<<CG, 256>>>(gx, W[2][0], W[2][1], W[2][2],
                         B[2][0], B[2][1], B[2][2], s0, s1, s2, NN);
    k_conv1<<<NG, 256>>>(s0, s1, s2, rs1, e1, rs2, e2, x3, NN);

    // ---- readout + outputs ----
    k_readout<<<NGRAPH, 256>>>(x3, (float*)d_out, out_size);
    k_copy_out<<<NG, 256>>>(x3, (float*)d_out, out_size);
}

// round 2
// speedup vs baseline: 1.3681x; 1.3681x over previous
#include <cuda_runtime.h>
#include <cuda_fp16.h>
#include <cstdint>

// ---------------------------------------------------------------------------
// DiGCN on GB300 — R2.
//  * y1/y2 conv gather tables stored fp16 (halves L2 gather traffic, tables
//    become fully L2-resident: 51MB total vs 126MB L2).
//  * CSR build overlapped with GEMM1 via side streams (graph-captured fork/join).
//  * Convs use coalesced edge loads + warp shfl broadcast.
// ---------------------------------------------------------------------------

#define N_NODES   200000
#define N_EDGES   3200000
#define NPG       50000
#define NGRAPH    4
#define HID       64

// ---------------- scratch (static device memory) ----------------------------
__device__ float  g_y0[(size_t)N_NODES * HID];
__device__ __half g_y1h[(size_t)N_NODES * HID];
__device__ __half g_y2h[(size_t)N_NODES * HID];
__device__ float  g_x [(size_t)N_NODES * HID];

__device__ int   g_deg1[N_NODES];
__device__ int   g_deg2[N_NODES];
__device__ int   g_rs1[N_NODES + 1];
__device__ int   g_rs2[N_NODES + 1];
__device__ int   g_bsum1[128];
__device__ int   g_bsum2[128];
__device__ int2  g_e1[N_EDGES];
__device__ int2  g_e2[N_EDGES];

__device__ float g_s0[N_NODES];
__device__ float g_s1[N_NODES];
__device__ float g_s2[N_NODES];
__device__ float g_x3[N_NODES];

// ---------------- helpers ----------------------------------------------------
__device__ __forceinline__ void fma2(unsigned long long &d,
                                     unsigned long long a,
                                     unsigned long long b) {
    asm("fma.rn.f32x2 %0, %1, %2, %0;" : "+l"(d) : "l"(a), "l"(b));
}
__device__ __forceinline__ unsigned long long rep2(float x) {
    unsigned long long r;
    unsigned u = __float_as_uint(x);
    asm("mov.b64 %0, {%1, %1};" : "=l"(r) : "r"(u));
    return r;
}

// ---------------- CSR build --------------------------------------------------
__global__ void k_zero(int* __restrict__ p, int n) {
    int i = blockIdx.x * blockDim.x + threadIdx.x;
    if (i < n) p[i] = 0;
}

__global__ void k_hist(const int* __restrict__ dst, int* __restrict__ deg, int E) {
    int e = blockIdx.x * blockDim.x + threadIdx.x;
    if (e < E) atomicAdd(&deg[dst[e]], 1);
}

__global__ void k_scan_sums(const int* __restrict__ deg, int* __restrict__ bsum, int n) {
    __shared__ int sh[16];
    int tid = threadIdx.x;
    int base = blockIdx.x * 2048 + tid * 4;
    int s = 0;
#pragma unroll
    for (int c = 0; c < 4; ++c) if (base + c < n) s += deg[base + c];
#pragma unroll
    for (int o = 16; o; o >>= 1) s += __shfl_xor_sync(0xffffffffu, s, o);
    if ((tid & 31) == 0) sh[tid >> 5] = s;
    __syncthreads();
    if (tid < 16) {
        int v = sh[tid];
#pragma unroll
        for (int o = 8; o; o >>= 1) v += __shfl_xor_sync(0x0000ffffu, v, o);
        if (tid == 0) bsum[blockIdx.x] = v;
    }
}

// parallel exclusive scan of <=128 block sums
__global__ void k_scan_bsum(int* __restrict__ bsum, int nb) {
    __shared__ int ws[4];
    int tid = threadIdx.x;            // 128 threads
    int lane = tid & 31, w = tid >> 5;
    int orig = (tid < nb) ? bsum[tid] : 0;
    int v = orig;
#pragma unroll
    for (int o = 1; o < 32; o <<= 1) {
        int t = __shfl_up_sync(0xffffffffu, v, o);
        if (lane >= o) v += t;
    }
    if (lane == 31) ws[w] = v;
    __syncthreads();
    if (tid == 0) { int a = 0; for (int i = 0; i < 4; ++i) { int t = ws[i]; ws[i] = a; a += t; } }
    __syncthreads();
    v += ws[w];
    if (tid < nb) bsum[tid] = v - orig;   // exclusive
}

__global__ void k_scan_write(int* __restrict__ deg, const int* __restrict__ bsum,
                             int* __restrict__ rs, int n, int total) {
    __shared__ int wsum[16];
    int tid = threadIdx.x;
    int lane = tid & 31, wid = tid >> 5;
    int base = blockIdx.x * 2048 + tid * 4;
    int v[4]; int s = 0;
#pragma unroll
    for (int c = 0; c < 4; ++c) { v[c] = (base + c < n) ? deg[base + c] : 0; s += v[c]; }
    int si = s;
#pragma unroll
    for (int o = 1; o < 32; o <<= 1) {
        int t = __shfl_up_sync(0xffffffffu, si, o);
        if (lane >= o) si += t;
    }
    if (lane == 31) wsum[wid] = si;
    __syncthreads();
    if (tid < 16) {
        int t = wsum[tid];
#pragma unroll
        for (int o = 1; o < 16; o <<= 1) {
            int u = __shfl_up_sync(0x0000ffffu, t, o);
            if (tid >= o) t += u;
        }
        wsum[tid] = t;
    }
    __syncthreads();
    int bbase = (wid == 0) ? 0 : wsum[wid - 1];
    int off = bsum[blockIdx.x] + bbase + (si - s);
#pragma unroll
    for (int c = 0; c < 4; ++c) {
        if (base + c < n) { rs[base + c] = off; deg[base + c] = off; off += v[c]; }
    }
    if (blockIdx.x == 0 && tid == 0) rs[n] = total;
}

__global__ void k_fill(const int* __restrict__ src, const int* __restrict__ dst,
                       const float* __restrict__ w, int* __restrict__ cur,
                       int2* __restrict__ out, int E) {
    int e = blockIdx.x * blockDim.x + threadIdx.x;
    if (e < E) {
        int pos = atomicAdd(&cur[dst[e]], 1);
        out[pos] = make_int2(src[e], __float_as_int(w[e]));
    }
}

// ---------------- GEMM: [M x K] @ [K x 192] -> Y0(f32) | Y1h,Y2h (fp16) -----
template <int K>
__global__ void __launch_bounds__(256, 1)
k_gemm(const float* __restrict__ X,
       const float* __restrict__ W0, const float* __restrict__ W1, const float* __restrict__ W2,
       const float* __restrict__ B0, const float* __restrict__ B1, const float* __restrict__ B2,
       float* __restrict__ Y0, __half* __restrict__ Y1h, __half* __restrict__ Y2h, int M)
{
    extern __shared__ float smem[];
    float* Xst = smem;              // [K][128]
    float* Ws  = smem + K * 128;    // [K][192]
    float* cb  = Ws + K * 192;      // [64]

    const int tid = threadIdx.x;
    const int r0  = blockIdx.x * 128;

    if (tid < 64) cb[tid] = B0[tid] + B1[tid] + B2[tid];

#pragma unroll
    for (int p = 0; p < K / 8; ++p) {
        int idx = p * 256 + tid;
        int row = idx & 127;
        int kc  = idx >> 7;
        float4 v = make_float4(0.f, 0.f, 0.f, 0.f);
        int grow = r0 + row;
        if (grow < M) v = *reinterpret_cast<const float4*>(&X[(size_t)grow * K + kc * 4]);
        Xst[(kc * 4 + 0) * 128 + row] = v.x;
        Xst[(kc * 4 + 1) * 128 + row] = v.y;
        Xst[(kc * 4 + 2) * 128 + row] = v.z;
        Xst[(kc * 4 + 3) * 128 + row] = v.w;
    }
#pragma unroll
    for (int p = 0; p < (K * 48) / 256; ++p) {
        int idx = p * 256 + tid;
        int j4 = idx % 48, k = idx / 48;
        int j = j4 * 4;
        const float* Wm = (j < 64) ? W0 : ((j < 128) ? W1 : W2);
        int jj = j & 63;
        float4 v = *reinterpret_cast<const float4*>(&Wm[k * 64 + jj]);
        *reinterpret_cast<float4*>(&Ws[k * 192 + j]) = v;
    }
    __syncthreads();

    const int tx = tid & 15, ty = tid >> 4;
    const int mb = ty * 8, nb = tx * 12;

    unsigned long long acc[4][12];
#pragma unroll
    for (int p = 0; p < 4; ++p)
#pragma unroll
        for (int j = 0; j < 12; ++j) acc[p][j] = 0ull;

#pragma unroll 8
    for (int k = 0; k < K; ++k) {
        const unsigned long long* ap =
            reinterpret_cast<const unsigned long long*>(&Xst[k * 128 + mb]);
        unsigned long long a0 = ap[0], a1 = ap[1], a2 = ap[2], a3 = ap[3];
        float4 b0 = *reinterpret_cast<const float4*>(&Ws[k * 192 + nb]);
        float4 b1 = *reinterpret_cast<const float4*>(&Ws[k * 192 + nb + 4]);
        float4 b2 = *reinterpret_cast<const float4*>(&Ws[k * 192 + nb + 8]);
        unsigned long long r[12];
        r[0] = rep2(b0.x); r[1] = rep2(b0.y); r[2]  = rep2(b0.z); r[3]  = rep2(b0.w);
        r[4] = rep2(b1.x); r[5] = rep2(b1.y); r[6]  = rep2(b1.z); r[7]  = rep2(b1.w);
        r[8] = rep2(b2.x); r[9] = rep2(b2.y); r[10] = rep2(b2.z); r[11] = rep2(b2.w);
#pragma unroll
        for (int j = 0; j < 12; ++j) {
            fma2(acc[0][j], a0, r[j]);
            fma2(acc[1][j], a1, r[j]);
            fma2(acc[2][j], a2, r[j]);
            fma2(acc[3][j], a3, r[j]);
        }
    }

#pragma unroll
    for (int p = 0; p < 4; ++p) {
#pragma unroll
        for (int h = 0; h < 2; ++h) {
            int row = r0 + mb + 2 * p + h;
            if (row >= M) continue;
#pragma unroll
            for (int j = 0; j < 12; j += 2) {
                unsigned u0 = (h == 0) ? (unsigned)acc[p][j]     : (unsigned)(acc[p][j] >> 32);
                unsigned u1 = (h == 0) ? (unsigned)acc[p][j + 1] : (unsigned)(acc[p][j + 1] >> 32);
                float f0 = __uint_as_float(u0);
                float f1 = __uint_as_float(u1);
                int col = nb + j;   // always even; region boundaries (64,128) pair-aligned
                if (col < 64) {
                    float2 o = make_float2(f0 + cb[col], f1 + cb[col + 1]);
                    *reinterpret_cast<float2*>(&Y0[(size_t)row * 64 + col]) = o;
                } else if (col < 128) {
                    *reinterpret_cast<__half2*>(&Y1h[(size_t)row * 64 + col - 64]) =
                        __floats2half2_rn(f0, f1);
                } else {
                    *reinterpret_cast<__half2*>(&Y2h[(size_t)row * 64 + col - 128]) =
                        __floats2half2_rn(f0, f1);
                }
            }
        }
    }
}

// ---------------- conv (hidden=64, fp16 tables): warp per node ---------------
__device__ __forceinline__ void conv_seg(const __half* __restrict__ yt,
                                         const int* __restrict__ rs,
                                         const int2* __restrict__ ee,
                                         int n, int lane, float2& acc)
{
    int p = rs[n], pe = rs[n + 1];
    while (p < pe) {
        int m = pe - p;
        int cnt = (m < 32) ? m : 32;
        int2 e = (lane < m) ? __ldg(&ee[p + lane]) : make_int2(0, 0);
        int j = 0;
        for (; j + 2 <= cnt; j += 2) {
            int   sA = __shfl_sync(0xffffffffu, e.x, j);
            float wA = __int_as_float(__shfl_sync(0xffffffffu, e.y, j));
            int   sB = __shfl_sync(0xffffffffu, e.x, j + 1);
            float wB = __int_as_float(__shfl_sync(0xffffffffu, e.y, j + 1));
            __half2 hA = *reinterpret_cast<const __half2*>(yt + (size_t)sA * 64 + lane * 2);
            __half2 hB = *reinterpret_cast<const __half2*>(yt + (size_t)sB * 64 + lane * 2);
            float2 vA = __half22float2(hA);
            float2 vB = __half22float2(hB);
            acc.x = fmaf(wA, vA.x, acc.x); acc.y = fmaf(wA, vA.y, acc.y);
            acc.x = fmaf(wB, vB.x, acc.x); acc.y = fmaf(wB, vB.y, acc.y);
        }
        if (j < cnt) {
            int   sA = __shfl_sync(0xffffffffu, e.x, j);
            float wA = __int_as_float(__shfl_sync(0xffffffffu, e.y, j));
            __half2 hA = *reinterpret_cast<const __half2*>(yt + (size_t)sA * 64 + lane * 2);
            float2 vA = __half22float2(hA);
            acc.x = fmaf(wA, vA.x, acc.x); acc.y = fmaf(wA, vA.y, acc.y);
        }
        p += cnt;
    }
}

__global__ void k_conv64(const float* __restrict__ y0,
                         const __half* __restrict__ y1, const __half* __restrict__ y2,
                         const int* __restrict__ rs1, const int2* __restrict__ e1,
                         const int* __restrict__ rs2, const int2* __restrict__ e2,
                         float* __restrict__ xout, int M)
{
    int n = (blockIdx.x * blockDim.x + threadIdx.x) >> 5;
    if (n >= M) return;
    int lane = threadIdx.x & 31;
    float2 acc = *reinterpret_cast<const float2*>(&y0[(size_t)n * 64 + lane * 2]);
    conv_seg(y1, rs1, e1, n, lane, acc);
    conv_seg(y2, rs2, e2, n, lane, acc);
    *reinterpret_cast<float2*>(&xout[(size_t)n * 64 + lane * 2]) = acc;
}

// ---------------- block3 GEMM (64 -> 3 scalars): warp per node ---------------
__global__ void k_gemm3(const float* __restrict__ X,
                        const float* __restrict__ w0, const float* __restrict__ w1,
                        const float* __restrict__ w2,
                        const float* __restrict__ b0, const float* __restrict__ b1,
                        const float* __restrict__ b2,
                        float* __restrict__ s0, float* __restrict__ s1,
                        float* __restrict__ s2, int M)
{
    __shared__ float ws[3][64];
    int tid = threadIdx.x;
    if (tid < 64) { ws[0][tid] = w0[tid]; ws[1][tid] = w1[tid]; ws[2][tid] = w2[tid]; }
    __syncthreads();
    int n = blockIdx.x * (blockDim.x >> 5) + (tid >> 5);
    if (n >= M) return;
    int lane = tid & 31;
    float2 xv = *reinterpret_cast<const float2*>(&X[(size_t)n * 64 + lane * 2]);
    float p0 = xv.x * ws[0][2 * lane] + xv.y * ws[0][2 * lane + 1];
    float p1 = xv.x * ws[1][2 * lane] + xv.y * ws[1][2 * lane + 1];
    float p2 = xv.x * ws[2][2 * lane] + xv.y * ws[2][2 * lane + 1];
#pragma unroll
    for (int o = 16; o; o >>= 1) {
        p0 += __shfl_xor_sync(0xffffffffu, p0, o);
        p1 += __shfl_xor_sync(0xffffffffu, p1, o);
        p2 += __shfl_xor_sync(0xffffffffu, p2, o);
    }
    if (lane == 0) {
        s0[n] = p0 + (b0[0] + b1[0] + b2[0]);
        s1[n] = p1;
        s2[n] = p2;
    }
}

// ---------------- block3 conv: warp per node, lane-parallel edges ------------
__global__ void k_conv1(const float* __restrict__ s0, const float* __restrict__ s1,
                        const float* __restrict__ s2,
                        const int* __restrict__ rs1, const int2* __restrict__ e1,
                        const int* __restrict__ rs2, const int2* __restrict__ e2,
                        float* __restrict__ x3, int M)
{
    int n = (blockIdx.x * blockDim.x + threadIdx.x) >> 5;
    if (n >= M) return;
    int lane = threadIdx.x & 31;
    float acc = 0.f;
    for (int p = rs1[n] + lane, pe = rs1[n + 1]; p < pe; p += 32) {
        int2 a = __ldg(&e1[p]);
        acc = fmaf(__int_as_float(a.y), __ldg(&s1[a.x]), acc);
    }
    for (int p = rs2[n] + lane, pe = rs2[n + 1]; p < pe; p += 32) {
        int2 a = __ldg(&e2[p]);
        acc = fmaf(__int_as_float(a.y), __ldg(&s2[a.x]), acc);
    }
#pragma unroll
    for (int o = 16; o; o >>= 1) acc += __shfl_xor_sync(0xffffffffu, acc, o);
    if (lane == 0) x3[n] = s0[n] + acc;
}

// ---------------- readout + output copy --------------------------------------
__global__ void k_readout(const float* __restrict__ x3, float* __restrict__ out,
                          int out_size)
{
    __shared__ float sh[256];
    int g = blockIdx.x;
    float m = -3.402823466e38f;
    for (int i = threadIdx.x; i < NPG; i += blockDim.x)
        m = fmaxf(m, x3[g * NPG + i]);
    sh[threadIdx.x] = m;
    __syncthreads();
    for (int s = 128; s; s >>= 1) {
        if (threadIdx.x < s) sh[threadIdx.x] = fmaxf(sh[threadIdx.x], sh[threadIdx.x + s]);
        __syncthreads();
    }
    if (threadIdx.x == 0 && g < out_size) out[g] = sh[0];
}

__global__ void k_copy_out(const float* __restrict__ x3, float* __restrict__ out,
                           int out_size)
{
    int i = blockIdx.x * blockDim.x + threadIdx.x;
    if (i >= N_NODES) return;
    float v = x3[i];
    if (4 + i < out_size)            out[4 + i] = v;
    if (4 + N_NODES + i < out_size)  out[4 + N_NODES + i] = v;
}

// ---------------------------------------------------------------------------
extern "C" void kernel_launch(void* const* d_in, const int* in_sizes, int n_in,
                              void* d_out, int out_size)
{
    const int E = N_EDGES, NN = N_NODES;

    const float* x   = (const float*)d_in[0];
    const int*   ei1 = (const int*)  d_in[1];
    const float* ew1 = (const float*)d_in[2];
    const int*   ei2 = (const int*)  d_in[3];
    const float* ew2 = (const float*)d_in[4];
    int base = (in_sizes[5] == 1) ? 6 : 5;
    const float* W[3][3]; const float* B[3][3];
    for (int blk = 0; blk < 3; ++blk)
        for (int part = 0; part < 3; ++part) {
            W[blk][part] = (const float*)d_in[base + blk * 6 + part * 2];
            B[blk][part] = (const float*)d_in[base + blk * 6 + part * 2 + 1];
        }

    float *y0, *gx, *s0, *s1, *s2, *x3;
    __half *y1h, *y2h;
    int *deg1, *deg2, *rs1, *rs2, *bs1, *bs2;
    int2 *e1, *e2;
    cudaGetSymbolAddress((void**)&y0, g_y0);
    cudaGetSymbolAddress((void**)&y1h, g_y1h);
    cudaGetSymbolAddress((void**)&y2h, g_y2h);
    cudaGetSymbolAddress((void**)&gx, g_x);
    cudaGetSymbolAddress((void**)&s0, g_s0);
    cudaGetSymbolAddress((void**)&s1, g_s1);
    cudaGetSymbolAddress((void**)&s2, g_s2);
    cudaGetSymbolAddress((void**)&x3, g_x3);
    cudaGetSymbolAddress((void**)&deg1, g_deg1);
    cudaGetSymbolAddress((void**)&deg2, g_deg2);
    cudaGetSymbolAddress((void**)&rs1, g_rs1);
    cudaGetSymbolAddress((void**)&rs2, g_rs2);
    cudaGetSymbolAddress((void**)&bs1, g_bsum1);
    cudaGetSymbolAddress((void**)&bs2, g_bsum2);
    cudaGetSymbolAddress((void**)&e1, g_e1);
    cudaGetSymbolAddress((void**)&e2, g_e2);

    // one-time host resources (streams/events; no device memory)
    static cudaStream_t sA = nullptr, sB = nullptr;
    static cudaEvent_t evRoot, evA, evB, evX3, evCopy;
    if (!sA) {
        cudaStreamCreateWithFlags(&sA, cudaStreamNonBlocking);
        cudaStreamCreateWithFlags(&sB, cudaStreamNonBlocking);
        cudaEventCreateWithFlags(&evRoot, cudaEventDisableTiming);
        cudaEventCreateWithFlags(&evA,    cudaEventDisableTiming);
        cudaEventCreateWithFlags(&evB,    cudaEventDisableTiming);
        cudaEventCreateWithFlags(&evX3,   cudaEventDisableTiming);
        cudaEventCreateWithFlags(&evCopy, cudaEventDisableTiming);
    }

    const int smem128 = (128 * 128 + 128 * 192 + 64) * 4;
    const int smem64  = (64 * 128 + 64 * 192 + 64) * 4;
    cudaFuncSetAttribute(k_gemm<128>, cudaFuncAttributeMaxDynamicSharedMemorySize, smem128);
    cudaFuncSetAttribute(k_gemm<64>,  cudaFuncAttributeMaxDynamicSharedMemorySize, smem64);

    const int SB = (NN + 2047) / 2048;
    const int EG = (E + 255) / 256;
    const int NG = (NN + 255) / 256;
    const int GG = (NN + 127) / 128;
    const int CG = (NN * 32 + 255) / 256;

    // fork: CSR pipelines on side streams, GEMM1 on main stream
    cudaEventRecord(evRoot, 0);
    cudaStreamWaitEvent(sA, evRoot, 0);
    cudaStreamWaitEvent(sB, evRoot, 0);

    k_zero<<<NG, 256, 0, sA>>>(deg1, NN);
    k_hist<<<EG, 256, 0, sA>>>(ei1 + E, deg1, E);
    k_scan_sums<<<SB, 512, 0, sA>>>(deg1, bs1, NN);
    k_scan_bsum<<<1, 128, 0, sA>>>(bs1, SB);
    k_scan_write<<<SB, 512, 0, sA>>>(deg1, bs1, rs1, NN, E);
    k_fill<<<EG, 256, 0, sA>>>(ei1, ei1 + E, ew1, deg1, e1, E);
    cudaEventRecord(evA, sA);

    k_zero<<<NG, 256, 0, sB>>>(deg2, NN);
    k_hist<<<EG, 256, 0, sB>>>(ei2 + E, deg2, E);
    k_scan_sums<<<SB, 512, 0, sB>>>(deg2, bs2, NN);
    k_scan_bsum<<<1, 128, 0, sB>>>(bs2, SB);
    k_scan_write<<<SB, 512, 0, sB>>>(deg2, bs2, rs2, NN, E);
    k_fill<<<EG, 256, 0, sB>>>(ei2, ei2 + E, ew2, deg2, e2, E);
    cudaEventRecord(evB, sB);

    k_gemm<128><<<GG, 256, smem128>>>(x, W[0][0], W[0][1], W[0][2],
                                      B[0][0], B[0][1], B[0][2],
                                      y0, y1h, y2h, NN);

    // join
    cudaStreamWaitEvent(0, evA, 0);
    cudaStreamWaitEvent(0, evB, 0);

    k_conv64<<<CG, 256>>>(y0, y1h, y2h, rs1, e1, rs2, e2, gx, NN);

    k_gemm<64><<<GG, 256, smem64>>>(gx, W[1][0], W[1][1], W[1][2],
                                    B[1][0], B[1][1], B[1][2],
                                    y0, y1h, y2h, NN);
    k_conv64<<<CG, 256>>>(y0, y1h, y2h, rs1, e1, rs2, e2, gx, NN);

    k_gemm3<<<CG, 256>>>(gx, W[2][0], W[2][1], W[2][2],
                         B[2][0], B[2][1], B[2][2], s0, s1, s2, NN);
    k_conv1<<<CG, 256>>>(s0, s1, s2, rs1, e1, rs2, e2, x3, NN);

    // tail: copy_out on side stream, readout on main, then rejoin
    cudaEventRecord(evX3, 0);
    cudaStreamWaitEvent(sA, evX3, 0);
    k_copy_out<<<NG, 256, 0, sA>>>(x3, (float*)d_out, out_size);
    cudaEventRecord(evCopy, sA);

    k_readout<<<NGRAPH, 256>>>(x3, (float*)d_out, out_size);
    cudaStreamWaitEvent(0, evCopy, 0);
}

// round 3
// speedup vs baseline: 1.3921x; 1.0175x over previous
#include <cuda_runtime.h>
#include <cuda_fp16.h>
#include <cstdint>

// ---------------------------------------------------------------------------
// DiGCN on GB300 — R3.
//  * Streaming traffic (y0, xout, edge lists, GEMM X/Y0) marked evict-first
//    (__ldcs/__stcs) so fp16 gather tables (51MB) stay L2-resident.
//  * conv64: 2-edge-parallel, 16 lanes/edge, uint2 (8B) gathers.
// ---------------------------------------------------------------------------

#define N_NODES   200000
#define N_EDGES   3200000
#define NPG       50000
#define NGRAPH    4
#define HID       64

__device__ float  g_y0[(size_t)N_NODES * HID];
__device__ __half g_y1h[(size_t)N_NODES * HID];
__device__ __half g_y2h[(size_t)N_NODES * HID];
__device__ float  g_x [(size_t)N_NODES * HID];

__device__ int   g_deg1[N_NODES];
__device__ int   g_deg2[N_NODES];
__device__ int   g_rs1[N_NODES + 1];
__device__ int   g_rs2[N_NODES + 1];
__device__ int   g_bsum1[128];
__device__ int   g_bsum2[128];
__device__ int2  g_e1[N_EDGES];
__device__ int2  g_e2[N_EDGES];

__device__ float g_s0[N_NODES];
__device__ float g_s1[N_NODES];
__device__ float g_s2[N_NODES];
__device__ float g_x3[N_NODES];

// ---------------- helpers ----------------------------------------------------
__device__ __forceinline__ void fma2(unsigned long long &d,
                                     unsigned long long a,
                                     unsigned long long b) {
    asm("fma.rn.f32x2 %0, %1, %2, %0;" : "+l"(d) : "l"(a), "l"(b));
}
__device__ __forceinline__ unsigned long long rep2(float x) {
    unsigned long long r;
    unsigned u = __float_as_uint(x);
    asm("mov.b64 %0, {%1, %1};" : "=l"(r) : "r"(u));
    return r;
}

// ---------------- CSR build --------------------------------------------------
__global__ void k_zero(int* __restrict__ p, int n) {
    int i = blockIdx.x * blockDim.x + threadIdx.x;
    if (i < n) p[i] = 0;
}

__global__ void k_hist(const int* __restrict__ dst, int* __restrict__ deg, int E) {
    int e = blockIdx.x * blockDim.x + threadIdx.x;
    if (e < E) atomicAdd(&deg[__ldcs(&dst[e])], 1);
}

__global__ void k_scan_sums(const int* __restrict__ deg, int* __restrict__ bsum, int n) {
    __shared__ int sh[16];
    int tid = threadIdx.x;
    int base = blockIdx.x * 2048 + tid * 4;
    int s = 0;
#pragma unroll
    for (int c = 0; c < 4; ++c) if (base + c < n) s += deg[base + c];
#pragma unroll
    for (int o = 16; o; o >>= 1) s += __shfl_xor_sync(0xffffffffu, s, o);
    if ((tid & 31) == 0) sh[tid >> 5] = s;
    __syncthreads();
    if (tid < 16) {
        int v = sh[tid];
#pragma unroll
        for (int o = 8; o; o >>= 1) v += __shfl_xor_sync(0x0000ffffu, v, o);
        if (tid == 0) bsum[blockIdx.x] = v;
    }
}

__global__ void k_scan_bsum(int* __restrict__ bsum, int nb) {
    __shared__ int ws[4];
    int tid = threadIdx.x;            // 128 threads
    int lane = tid & 31, w = tid >> 5;
    int orig = (tid < nb) ? bsum[tid] : 0;
    int v = orig;
#pragma unroll
    for (int o = 1; o < 32; o <<= 1) {
        int t = __shfl_up_sync(0xffffffffu, v, o);
        if (lane >= o) v += t;
    }
    if (lane == 31) ws[w] = v;
    __syncthreads();
    if (tid == 0) { int a = 0; for (int i = 0; i < 4; ++i) { int t = ws[i]; ws[i] = a; a += t; } }
    __syncthreads();
    v += ws[w];
    if (tid < nb) bsum[tid] = v - orig;
}

__global__ void k_scan_write(int* __restrict__ deg, const int* __restrict__ bsum,
                             int* __restrict__ rs, int n, int total) {
    __shared__ int wsum[16];
    int tid = threadIdx.x;
    int lane = tid & 31, wid = tid >> 5;
    int base = blockIdx.x * 2048 + tid * 4;
    int v[4]; int s = 0;
#pragma unroll
    for (int c = 0; c < 4; ++c) { v[c] = (base + c < n) ? deg[base + c] : 0; s += v[c]; }
    int si = s;
#pragma unroll
    for (int o = 1; o < 32; o <<= 1) {
        int t = __shfl_up_sync(0xffffffffu, si, o);
        if (lane >= o) si += t;
    }
    if (lane == 31) wsum[wid] = si;
    __syncthreads();
    if (tid < 16) {
        int t = wsum[tid];
#pragma unroll
        for (int o = 1; o < 16; o <<= 1) {
            int u = __shfl_up_sync(0x0000ffffu, t, o);
            if (tid >= o) t += u;
        }
        wsum[tid] = t;
    }
    __syncthreads();
    int bbase = (wid == 0) ? 0 : wsum[wid - 1];
    int off = bsum[blockIdx.x] + bbase + (si - s);
#pragma unroll
    for (int c = 0; c < 4; ++c) {
        if (base + c < n) { rs[base + c] = off; deg[base + c] = off; off += v[c]; }
    }
    if (blockIdx.x == 0 && tid == 0) rs[n] = total;
}

__global__ void k_fill(const int* __restrict__ src, const int* __restrict__ dst,
                       const float* __restrict__ w, int* __restrict__ cur,
                       int2* __restrict__ out, int E) {
    int e = blockIdx.x * blockDim.x + threadIdx.x;
    if (e < E) {
        int pos = atomicAdd(&cur[__ldcs(&dst[e])], 1);
        out[pos] = make_int2(__ldcs(&src[e]), __float_as_int(__ldcs(&w[e])));
    }
}

// ---------------- GEMM: [M x K] @ [K x 192] -> Y0(f32) | Y1h,Y2h (fp16) -----
template <int K>
__global__ void __launch_bounds__(256, 1)
k_gemm(const float* __restrict__ X,
       const float* __restrict__ W0, const float* __restrict__ W1, const float* __restrict__ W2,
       const float* __restrict__ B0, const float* __restrict__ B1, const float* __restrict__ B2,
       float* __restrict__ Y0, __half* __restrict__ Y1h, __half* __restrict__ Y2h, int M)
{
    extern __shared__ float smem[];
    float* Xst = smem;              // [K][128]
    float* Ws  = smem + K * 128;    // [K][192]
    float* cb  = Ws + K * 192;      // [64]

    const int tid = threadIdx.x;
    const int r0  = blockIdx.x * 128;

    if (tid < 64) cb[tid] = B0[tid] + B1[tid] + B2[tid];

#pragma unroll
    for (int p = 0; p < K / 8; ++p) {
        int idx = p * 256 + tid;
        int row = idx & 127;
        int kc  = idx >> 7;
        float4 v = make_float4(0.f, 0.f, 0.f, 0.f);
        int grow = r0 + row;
        if (grow < M) v = __ldcs(reinterpret_cast<const float4*>(&X[(size_t)grow * K + kc * 4]));
        Xst[(kc * 4 + 0) * 128 + row] = v.x;
        Xst[(kc * 4 + 1) * 128 + row] = v.y;
        Xst[(kc * 4 + 2) * 128 + row] = v.z;
        Xst[(kc * 4 + 3) * 128 + row] = v.w;
    }
#pragma unroll
    for (int p = 0; p < (K * 48) / 256; ++p) {
        int idx = p * 256 + tid;
        int j4 = idx % 48, k = idx / 48;
        int j = j4 * 4;
        const float* Wm = (j < 64) ? W0 : ((j < 128) ? W1 : W2);
        int jj = j & 63;
        float4 v = *reinterpret_cast<const float4*>(&Wm[k * 64 + jj]);
        *reinterpret_cast<float4*>(&Ws[k * 192 + j]) = v;
    }
    __syncthreads();

    const int tx = tid & 15, ty = tid >> 4;
    const int mb = ty * 8, nb = tx * 12;

    unsigned long long acc[4][12];
#pragma unroll
    for (int p = 0; p < 4; ++p)
#pragma unroll
        for (int j = 0; j < 12; ++j) acc[p][j] = 0ull;

#pragma unroll 8
    for (int k = 0; k < K; ++k) {
        const unsigned long long* ap =
            reinterpret_cast<const unsigned long long*>(&Xst[k * 128 + mb]);
        unsigned long long a0 = ap[0], a1 = ap[1], a2 = ap[2], a3 = ap[3];
        float4 b0 = *reinterpret_cast<const float4*>(&Ws[k * 192 + nb]);
        float4 b1 = *reinterpret_cast<const float4*>(&Ws[k * 192 + nb + 4]);
        float4 b2 = *reinterpret_cast<const float4*>(&Ws[k * 192 + nb + 8]);
        unsigned long long r[12];
        r[0] = rep2(b0.x); r[1] = rep2(b0.y); r[2]  = rep2(b0.z); r[3]  = rep2(b0.w);
        r[4] = rep2(b1.x); r[5] = rep2(b1.y); r[6]  = rep2(b1.z); r[7]  = rep2(b1.w);
        r[8] = rep2(b2.x); r[9] = rep2(b2.y); r[10] = rep2(b2.z); r[11] = rep2(b2.w);
#pragma unroll
        for (int j = 0; j < 12; ++j) {
            fma2(acc[0][j], a0, r[j]);
            fma2(acc[1][j], a1, r[j]);
            fma2(acc[2][j], a2, r[j]);
            fma2(acc[3][j], a3, r[j]);
        }
    }

#pragma unroll
    for (int p = 0; p < 4; ++p) {
#pragma unroll
        for (int h = 0; h < 2; ++h) {
            int row = r0 + mb + 2 * p + h;
            if (row >= M) continue;
#pragma unroll
            for (int j = 0; j < 12; j += 2) {
                unsigned u0 = (h == 0) ? (unsigned)acc[p][j]     : (unsigned)(acc[p][j] >> 32);
                unsigned u1 = (h == 0) ? (unsigned)acc[p][j + 1] : (unsigned)(acc[p][j + 1] >> 32);
                float f0 = __uint_as_float(u0);
                float f1 = __uint_as_float(u1);
                int col = nb + j;
                if (col < 64) {
                    float2 o = make_float2(f0 + cb[col], f1 + cb[col + 1]);
                    __stcs(reinterpret_cast<float2*>(&Y0[(size_t)row * 64 + col]), o);
                } else if (col < 128) {
                    *reinterpret_cast<__half2*>(&Y1h[(size_t)row * 64 + col - 64]) =
                        __floats2half2_rn(f0, f1);
                } else {
                    *reinterpret_cast<__half2*>(&Y2h[(size_t)row * 64 + col - 128]) =
                        __floats2half2_rn(f0, f1);
                }
            }
        }
    }
}

// ---------------- conv (hidden=64, fp16 tables): warp/node, 2 edges parallel -
__device__ __forceinline__ void conv_seg2(const __half* __restrict__ yt,
                                          const int* __restrict__ rs,
                                          const int2* __restrict__ ee,
                                          int n, int half, int sub, int lane,
                                          float4& acc)
{
    int p = __ldg(&rs[n]), pe = __ldg(&rs[n + 1]);
    while (p < pe) {
        int m = pe - p;
        int cnt = (m < 32) ? m : 32;
        int2 e = (lane < cnt) ? __ldcs(&ee[p + lane]) : make_int2(0, 0);
#pragma unroll 2
        for (int j = 0; j < cnt; j += 2) {
            int idx = j + half;
            int v = (idx < cnt);
            int sel = v ? idx : j;
            int   s = __shfl_sync(0xffffffffu, e.x, sel);
            float w = __int_as_float(__shfl_sync(0xffffffffu, e.y, sel));
            if (!v) w = 0.f;
            uint2 h = *reinterpret_cast<const uint2*>(yt + (size_t)s * 64 + sub * 4);
            float2 f0 = __half22float2(*reinterpret_cast<const __half2*>(&h.x));
            float2 f1 = __half22float2(*reinterpret_cast<const __half2*>(&h.y));
            acc.x = fmaf(w, f0.x, acc.x);
            acc.y = fmaf(w, f0.y, acc.y);
            acc.z = fmaf(w, f1.x, acc.z);
            acc.w = fmaf(w, f1.y, acc.w);
        }
        p += cnt;
    }
}

__global__ void k_conv64(const float* __restrict__ y0,
                         const __half* __restrict__ y1, const __half* __restrict__ y2,
                         const int* __restrict__ rs1, const int2* __restrict__ e1,
                         const int* __restrict__ rs2, const int2* __restrict__ e2,
                         float* __restrict__ xout, int M)
{
    int n = (blockIdx.x * blockDim.x + threadIdx.x) >> 5;
    if (n >= M) return;
    int lane = threadIdx.x & 31;
    int half = lane >> 4, sub = lane & 15;

    float4 acc = make_float4(0.f, 0.f, 0.f, 0.f);
    if (half == 0)
        acc = __ldcs(reinterpret_cast<const float4*>(&y0[(size_t)n * 64 + sub * 4]));

    conv_seg2(y1, rs1, e1, n, half, sub, lane, acc);
    conv_seg2(y2, rs2, e2, n, half, sub, lane, acc);

    acc.x += __shfl_xor_sync(0xffffffffu, acc.x, 16);
    acc.y += __shfl_xor_sync(0xffffffffu, acc.y, 16);
    acc.z += __shfl_xor_sync(0xffffffffu, acc.z, 16);
    acc.w += __shfl_xor_sync(0xffffffffu, acc.w, 16);
    if (half == 0)
        __stcs(reinterpret_cast<float4*>(&xout[(size_t)n * 64 + sub * 4]), acc);
}

// ---------------- block3 GEMM (64 -> 3 scalars): warp per node ---------------
__global__ void k_gemm3(const float* __restrict__ X,
                        const float* __restrict__ w0, const float* __restrict__ w1,
                        const float* __restrict__ w2,
                        const float* __restrict__ b0, const float* __restrict__ b1,
                        const float* __restrict__ b2,
                        float* __restrict__ s0, float* __restrict__ s1,
                        float* __restrict__ s2, int M)
{
    __shared__ float ws[3][64];
    int tid = threadIdx.x;
    if (tid < 64) { ws[0][tid] = w0[tid]; ws[1][tid] = w1[tid]; ws[2][tid] = w2[tid]; }
    __syncthreads();
    int n = blockIdx.x * (blockDim.x >> 5) + (tid >> 5);
    if (n >= M) return;
    int lane = tid & 31;
    float2 xv = __ldcs(reinterpret_cast<const float2*>(&X[(size_t)n * 64 + lane * 2]));
    float p0 = xv.x * ws[0][2 * lane] + xv.y * ws[0][2 * lane + 1];
    float p1 = xv.x * ws[1][2 * lane] + xv.y * ws[1][2 * lane + 1];
    float p2 = xv.x * ws[2][2 * lane] + xv.y * ws[2][2 * lane + 1];
#pragma unroll
    for (int o = 16; o; o >>= 1) {
        p0 += __shfl_xor_sync(0xffffffffu, p0, o);
        p1 += __shfl_xor_sync(0xffffffffu, p1, o);
        p2 += __shfl_xor_sync(0xffffffffu, p2, o);
    }
    if (lane == 0) {
        s0[n] = p0 + (b0[0] + b1[0] + b2[0]);
        s1[n] = p1;
        s2[n] = p2;
    }
}

// ---------------- block3 conv: warp per node, lane-parallel edges ------------
__global__ void k_conv1(const float* __restrict__ s0, const float* __restrict__ s1,
                        const float* __restrict__ s2,
                        const int* __restrict__ rs1, const int2* __restrict__ e1,
                        const int* __restrict__ rs2, const int2* __restrict__ e2,
                        float* __restrict__ x3, int M)
{
    int n = (blockIdx.x * blockDim.x + threadIdx.x) >> 5;
    if (n >= M) return;
    int lane = threadIdx.x & 31;
    float acc = 0.f;
    for (int p = __ldg(&rs1[n]) + lane, pe = __ldg(&rs1[n + 1]); p < pe; p += 32) {
        int2 a = __ldcs(&e1[p]);
        acc = fmaf(__int_as_float(a.y), __ldg(&s1[a.x]), acc);
    }
    for (int p = __ldg(&rs2[n]) + lane, pe = __ldg(&rs2[n + 1]); p < pe; p += 32) {
        int2 a = __ldcs(&e2[p]);
        acc = fmaf(__int_as_float(a.y), __ldg(&s2[a.x]), acc);
    }
#pragma unroll
    for (int o = 16; o; o >>= 1) acc += __shfl_xor_sync(0xffffffffu, acc, o);
    if (lane == 0) x3[n] = s0[n] + acc;
}

// ---------------- readout + output copy --------------------------------------
__global__ void k_readout(const float* __restrict__ x3, float* __restrict__ out,
                          int out_size)
{
    __shared__ float sh[256];
    int g = blockIdx.x;
    float m = -3.402823466e38f;
    for (int i = threadIdx.x; i < NPG; i += blockDim.x)
        m = fmaxf(m, x3[g * NPG + i]);
    sh[threadIdx.x] = m;
    __syncthreads();
    for (int s = 128; s; s >>= 1) {
        if (threadIdx.x < s) sh[threadIdx.x] = fmaxf(sh[threadIdx.x], sh[threadIdx.x + s]);
        __syncthreads();
    }
    if (threadIdx.x == 0 && g < out_size) out[g] = sh[0];
}

__global__ void k_copy_out(const float* __restrict__ x3, float* __restrict__ out,
                           int out_size)
{
    int i = blockIdx.x * blockDim.x + threadIdx.x;
    if (i >= N_NODES) return;
    float v = __ldg(&x3[i]);
    if (4 + i < out_size)            __stcs(&out[4 + i], v);
    if (4 + N_NODES + i < out_size)  __stcs(&out[4 + N_NODES + i], v);
}

// ---------------------------------------------------------------------------
extern "C" void kernel_launch(void* const* d_in, const int* in_sizes, int n_in,
                              void* d_out, int out_size)
{
    const int E = N_EDGES, NN = N_NODES;

    const float* x   = (const float*)d_in[0];
    const int*   ei1 = (const int*)  d_in[1];
    const float* ew1 = (const float*)d_in[2];
    const int*   ei2 = (const int*)  d_in[3];
    const float* ew2 = (const float*)d_in[4];
    int base = (in_sizes[5] == 1) ? 6 : 5;
    const float* W[3][3]; const float* B[3][3];
    for (int blk = 0; blk < 3; ++blk)
        for (int part = 0; part < 3; ++part) {
            W[blk][part] = (const float*)d_in[base + blk * 6 + part * 2];
            B[blk][part] = (const float*)d_in[base + blk * 6 + part * 2 + 1];
        }

    float *y0, *gx, *s0, *s1, *s2, *x3;
    __half *y1h, *y2h;
    int *deg1, *deg2, *rs1, *rs2, *bs1, *bs2;
    int2 *e1, *e2;
    cudaGetSymbolAddress((void**)&y0, g_y0);
    cudaGetSymbolAddress((void**)&y1h, g_y1h);
    cudaGetSymbolAddress((void**)&y2h, g_y2h);
    cudaGetSymbolAddress((void**)&gx, g_x);
    cudaGetSymbolAddress((void**)&s0, g_s0);
    cudaGetSymbolAddress((void**)&s1, g_s1);
    cudaGetSymbolAddress((void**)&s2, g_s2);
    cudaGetSymbolAddress((void**)&x3, g_x3);
    cudaGetSymbolAddress((void**)&deg1, g_deg1);
    cudaGetSymbolAddress((void**)&deg2, g_deg2);
    cudaGetSymbolAddress((void**)&rs1, g_rs1);
    cudaGetSymbolAddress((void**)&rs2, g_rs2);
    cudaGetSymbolAddress((void**)&bs1, g_bsum1);
    cudaGetSymbolAddress((void**)&bs2, g_bsum2);
    cudaGetSymbolAddress((void**)&e1, g_e1);
    cudaGetSymbolAddress((void**)&e2, g_e2);

    static cudaStream_t sA = nullptr, sB = nullptr;
    static cudaEvent_t evRoot, evA, evB, evX3, evCopy;
    if (!sA) {
        cudaStreamCreateWithFlags(&sA, cudaStreamNonBlocking);
        cudaStreamCreateWithFlags(&sB, cudaStreamNonBlocking);
        cudaEventCreateWithFlags(&evRoot, cudaEventDisableTiming);
        cudaEventCreateWithFlags(&evA,    cudaEventDisableTiming);
        cudaEventCreateWithFlags(&evB,    cudaEventDisableTiming);
        cudaEventCreateWithFlags(&evX3,   cudaEventDisableTiming);
        cudaEventCreateWithFlags(&evCopy, cudaEventDisableTiming);
    }

    const int smem128 = (128 * 128 + 128 * 192 + 64) * 4;
    const int smem64  = (64 * 128 + 64 * 192 + 64) * 4;
    cudaFuncSetAttribute(k_gemm<128>, cudaFuncAttributeMaxDynamicSharedMemorySize, smem128);
    cudaFuncSetAttribute(k_gemm<64>,  cudaFuncAttributeMaxDynamicSharedMemorySize, smem64);

    const int SB = (NN + 2047) / 2048;
    const int EG = (E + 255) / 256;
    const int NG = (NN + 255) / 256;
    const int GG = (NN + 127) / 128;
    const int CG = (NN * 32 + 255) / 256;

    cudaEventRecord(evRoot, 0);
    cudaStreamWaitEvent(sA, evRoot, 0);
    cudaStreamWaitEvent(sB, evRoot, 0);

    k_zero<<<NG, 256, 0, sA>>>(deg1, NN);
    k_hist<<<EG, 256, 0, sA>>>(ei1 + E, deg1, E);
    k_scan_sums<<<SB, 512, 0, sA>>>(deg1, bs1, NN);
    k_scan_bsum<<<1, 128, 0, sA>>>(bs1, SB);
    k_scan_write<<<SB, 512, 0, sA>>>(deg1, bs1, rs1, NN, E);
    k_fill<<<EG, 256, 0, sA>>>(ei1, ei1 + E, ew1, deg1, e1, E);
    cudaEventRecord(evA, sA);

    k_zero<<<NG, 256, 0, sB>>>(deg2, NN);
    k_hist<<<EG, 256, 0, sB>>>(ei2 + E, deg2, E);
    k_scan_sums<<<SB, 512, 0, sB>>>(deg2, bs2, NN);
    k_scan_bsum<<<1, 128, 0, sB>>>(bs2, SB);
    k_scan_write<<<SB, 512, 0, sB>>>(deg2, bs2, rs2, NN, E);
    k_fill<<<EG, 256, 0, sB>>>(ei2, ei2 + E, ew2, deg2, e2, E);
    cudaEventRecord(evB, sB);

    k_gemm<128><<<GG, 256, smem128>>>(x, W[0][0], W[0][1], W[0][2],
                                      B[0][0], B[0][1], B[0][2],
                                      y0, y1h, y2h, NN);

    cudaStreamWaitEvent(0, evA, 0);
    cudaStreamWaitEvent(0, evB, 0);

    k_conv64<<<CG, 256>>>(y0, y1h, y2h, rs1, e1, rs2, e2, gx, NN);

    k_gemm<64><<<GG, 256, smem64>>>(gx, W[1][0], W[1][1], W[1][2],
                                    B[1][0], B[1][1], B[1][2],
                                    y0, y1h, y2h, NN);
    k_conv64<<<CG, 256>>>(y0, y1h, y2h, rs1, e1, rs2, e2, gx, NN);

    k_gemm3<<<CG, 256>>>(gx, W[2][0], W[2][1], W[2][2],
                         B[2][0], B[2][1], B[2][2], s0, s1, s2, NN);
    k_conv1<<<CG, 256>>>(s0, s1, s2, rs1, e1, rs2, e2, x3, NN);

    cudaEventRecord(evX3, 0);
    cudaStreamWaitEvent(sA, evX3, 0);
    k_copy_out<<<NG, 256, 0, sA>>>(x3, (float*)d_out, out_size);
    cudaEventRecord(evCopy, sA);

    k_readout<<<NGRAPH, 256>>>(x3, (float*)d_out, out_size);
    cudaStreamWaitEvent(0, evCopy, 0);
}